// round 3
// baseline (speedup 1.0000x reference)
#include <cuda_runtime.h>

// RMSD quaternion loss: B=4096 batches, N=2048 atoms, 3 coords.
// Stage 1 (k1): per-batch reduction of R (3x3 cross-correlation) + squared norms. HBM-bound: 201 MB read.
// Stage 2 (k2): per-batch largest eigenvalue of the quaternion key matrix F via Newton
//               on the characteristic quartic l^4 + c2 l^2 + c1 l + c0, started from the
//               upper bound 2*sqrt(S) >= lmax (monotone convergence from above). FP64.
// Stage 3 (k3): final sum + sqrt.
// No atomics -> deterministic. No allocations: scratch lives in __device__ globals.

constexpr int BATCHES = 4096;
constexpr int NATOMS  = 2048;
constexpr int F4_PER_BATCH = NATOMS * 3 / 4;   // 1536 float4 per batch per tensor
constexpr int CHUNKS = NATOMS / 4;             // 512 chunks of 4 atoms (48 B each)
constexpr int K1_THREADS = 256;
constexpr int K2_THREADS = 128;
constexpr int K2_BLOCKS  = BATCHES / K2_THREADS; // 32

// scratch: SoA [10][BATCHES]: r00 r01 r02 r10 r11 r12 r20 r21 r22 sqn
__device__ float  g_scr[10 * BATCHES];
__device__ double g_part[K2_BLOCKS];

struct Acc10 { float a[10]; };

__device__ __forceinline__ void accum4(Acc10& s,
                                       const float4 a0, const float4 a1, const float4 a2,
                                       const float4 b0, const float4 b1, const float4 b2)
{
    const float px[4] = { a0.x, a0.w, a1.z, a2.y };
    const float py[4] = { a0.y, a1.x, a1.w, a2.z };
    const float pz[4] = { a0.z, a1.y, a2.x, a2.w };
    const float qx[4] = { b0.x, b0.w, b1.z, b2.y };
    const float qy[4] = { b0.y, b1.x, b1.w, b2.z };
    const float qz[4] = { b0.z, b1.y, b2.x, b2.w };

#pragma unroll
    for (int i = 0; i < 4; ++i) {
        s.a[0] = fmaf(px[i], qx[i], s.a[0]);
        s.a[1] = fmaf(px[i], qy[i], s.a[1]);
        s.a[2] = fmaf(px[i], qz[i], s.a[2]);
        s.a[3] = fmaf(py[i], qx[i], s.a[3]);
        s.a[4] = fmaf(py[i], qy[i], s.a[4]);
        s.a[5] = fmaf(py[i], qz[i], s.a[5]);
        s.a[6] = fmaf(pz[i], qx[i], s.a[6]);
        s.a[7] = fmaf(pz[i], qy[i], s.a[7]);
        s.a[8] = fmaf(pz[i], qz[i], s.a[8]);
        s.a[9] = fmaf(px[i], px[i], s.a[9]);
        s.a[9] = fmaf(py[i], py[i], s.a[9]);
        s.a[9] = fmaf(pz[i], pz[i], s.a[9]);
        s.a[9] = fmaf(qx[i], qx[i], s.a[9]);
        s.a[9] = fmaf(qy[i], qy[i], s.a[9]);
        s.a[9] = fmaf(qz[i], qz[i], s.a[9]);
    }
}

__global__ __launch_bounds__(K1_THREADS)
void k1_reduce(const float4* __restrict__ yp, const float4* __restrict__ yy)
{
    const int b = blockIdx.x;
    const float4* __restrict__ yp_b = yp + (size_t)b * F4_PER_BATCH;
    const float4* __restrict__ yy_b = yy + (size_t)b * F4_PER_BATCH;

    Acc10 s;
#pragma unroll
    for (int i = 0; i < 10; ++i) s.a[i] = 0.0f;

    // 512 chunks / 256 threads = exactly 2 chunks per thread. Unrolled: 12 LDG.128
    // issued up front per thread -> high MLP, latency hidden.
    {
        const int c0 = threadIdx.x;
        const int c1 = threadIdx.x + K1_THREADS;

        const float4 a00 = yp_b[c0 * 3 + 0];
        const float4 a01 = yp_b[c0 * 3 + 1];
        const float4 a02 = yp_b[c0 * 3 + 2];
        const float4 b00 = yy_b[c0 * 3 + 0];
        const float4 b01 = yy_b[c0 * 3 + 1];
        const float4 b02 = yy_b[c0 * 3 + 2];
        const float4 a10 = yp_b[c1 * 3 + 0];
        const float4 a11 = yp_b[c1 * 3 + 1];
        const float4 a12 = yp_b[c1 * 3 + 2];
        const float4 b10 = yy_b[c1 * 3 + 0];
        const float4 b11 = yy_b[c1 * 3 + 1];
        const float4 b12 = yy_b[c1 * 3 + 2];

        accum4(s, a00, a01, a02, b00, b01, b02);
        accum4(s, a10, a11, a12, b10, b11, b12);
    }

    // warp reduce all 10
#pragma unroll
    for (int i = 0; i < 10; ++i)
#pragma unroll
        for (int off = 16; off > 0; off >>= 1)
            s.a[i] += __shfl_down_sync(0xffffffffu, s.a[i], off);

    __shared__ float sm[K1_THREADS / 32][10];
    const int warp = threadIdx.x >> 5;
    const int lane = threadIdx.x & 31;
    if (lane == 0) {
#pragma unroll
        for (int i = 0; i < 10; ++i) sm[warp][i] = s.a[i];
    }
    __syncthreads();

    if (warp == 0) {
        float v[10];
#pragma unroll
        for (int i = 0; i < 10; ++i)
            v[i] = (lane < (K1_THREADS / 32)) ? sm[lane][i] : 0.0f;
#pragma unroll
        for (int i = 0; i < 10; ++i)
#pragma unroll
            for (int off = (K1_THREADS / 64); off > 0; off >>= 1)
                v[i] += __shfl_down_sync(0xffffffffu, v[i], off);
        if (lane == 0) {
#pragma unroll
            for (int i = 0; i < 10; ++i)
                g_scr[i * BATCHES + b] = v[i];
        }
    }
}

__device__ __forceinline__ double det3(double a, double b, double c,
                                       double d, double e, double f,
                                       double g, double h, double i)
{
    return a * (e * i - f * h) - b * (d * i - f * g) + c * (d * h - e * g);
}

__global__ __launch_bounds__(K2_THREADS)
void k2_eigen()
{
    const int b = blockIdx.x * K2_THREADS + threadIdx.x;

    const double r00 = g_scr[0 * BATCHES + b];
    const double r01 = g_scr[1 * BATCHES + b];
    const double r02 = g_scr[2 * BATCHES + b];
    const double r10 = g_scr[3 * BATCHES + b];
    const double r11 = g_scr[4 * BATCHES + b];
    const double r12 = g_scr[5 * BATCHES + b];
    const double r20 = g_scr[6 * BATCHES + b];
    const double r21 = g_scr[7 * BATCHES + b];
    const double r22 = g_scr[8 * BATCHES + b];
    const double sqn = g_scr[9 * BATCHES + b];

    const double S = r00*r00 + r01*r01 + r02*r02
                   + r10*r10 + r11*r11 + r12*r12
                   + r20*r20 + r21*r21 + r22*r22;
    const double c2 = -2.0 * S;
    const double detR = r00 * (r11 * r22 - r12 * r21)
                      - r01 * (r10 * r22 - r12 * r20)
                      + r02 * (r10 * r21 - r11 * r20);
    const double c1 = -8.0 * detR;

    // Quaternion key matrix F (symmetric, trace 0)
    const double F00 =  r00 + r11 + r22;
    const double F01 =  r12 - r21;
    const double F02 =  r20 - r02;
    const double F03 =  r01 - r10;
    const double F11 =  r00 - r11 - r22;
    const double F12 =  r01 + r10;
    const double F13 =  r02 + r20;
    const double F22 = -r00 + r11 - r22;
    const double F23 =  r12 + r21;
    const double F33 = -r00 - r11 + r22;

    // c0 = det(F): cofactor expansion along row 0 (symmetric F)
    const double M00 = det3(F11, F12, F13,  F12, F22, F23,  F13, F23, F33);
    const double M01 = det3(F01, F12, F13,  F02, F22, F23,  F03, F23, F33);
    const double M02 = det3(F01, F11, F13,  F02, F12, F23,  F03, F13, F33);
    const double M03 = det3(F01, F11, F12,  F02, F12, F22,  F03, F13, F23);
    const double c0 = F00 * M00 - F01 * M01 + F02 * M02 - F03 * M03;

    // Newton on P(l) = l^4 + c2 l^2 + c1 l + c0 from upper bound l0 = 2*sqrt(S) >= lmax.
    double lam = 2.0 * sqrt(S);
#pragma unroll 1
    for (int it = 0; it < 50; ++it) {
        const double l2 = lam * lam;
        const double p  = ((l2 + c2) * lam + c1) * lam + c0;
        const double dp = (4.0 * l2 + 2.0 * c2) * lam + c1;
        if (fabs(dp) < 1e-300) break;
        const double step = p / dp;
        lam -= step;
        if (fabs(step) < 1e-10 * fabs(lam) + 1e-14) break;
    }

    double sd = sqn - 2.0 * lam;

    // deterministic block tree reduce
    __shared__ double sdata[K2_THREADS];
    sdata[threadIdx.x] = sd;
    __syncthreads();
#pragma unroll
    for (int st = K2_THREADS / 2; st > 0; st >>= 1) {
        if (threadIdx.x < st) sdata[threadIdx.x] += sdata[threadIdx.x + st];
        __syncthreads();
    }
    if (threadIdx.x == 0) g_part[blockIdx.x] = sdata[0];
}

__global__ void k3_final(float* __restrict__ out)
{
    double v = (threadIdx.x < K2_BLOCKS) ? g_part[threadIdx.x] : 0.0;
#pragma unroll
    for (int off = 16; off > 0; off >>= 1)
        v += __shfl_down_sync(0xffffffffu, v, off);
    if (threadIdx.x == 0)
        out[0] = (float)sqrt(v / (double)NATOMS);
}

extern "C" void kernel_launch(void* const* d_in, const int* in_sizes, int n_in,
                              void* d_out, int out_size)
{
    const float4* yp = (const float4*)d_in[0]; // y_prime (B, N, 3)
    const float4* yy = (const float4*)d_in[1]; // y       (B, N, 3)
    float* out = (float*)d_out;

    k1_reduce<<<BATCHES, K1_THREADS>>>(yp, yy);
    k2_eigen<<<K2_BLOCKS, K2_THREADS>>>();
    k3_final<<<1, 32>>>(out);
}